// round 15
// baseline (speedup 1.0000x reference)
#include <cuda_runtime.h>
#include <cuda_fp16.h>
#include <cstdint>

#define C_      512
#define C2H     (C_ / 2)           // half2 units per spatial position (256)
#define HF      64
#define WF      256
#define P_      (HF * WF)          // 16384 spatial positions
#define NPOS    49                 // 7x7 samples
#define CH_BLK  128                // channels per block (box split in quarters)
#define NBOX    4                  // boxes processed per block (pipelined)
#define TILE_FLOATS (CH_BLK * NPOS)               // 6272 floats = 25088 bytes
// smem: meta double buffer (2*49 int4 offs + 2*49 int4 weights) + stage
#define SMEM_BYTES  (4 * NPOS * 16 + TILE_FLOATS * 4)  // 3136 + 25088 = 28224

// Transposed feats in fp16, PERMUTED channel pairing:
// unit u = 64*b + v holds channels {128b+v, 128b+v+64}; a half2 gather by
// thread v yields stage rows v and v+64 (lane word-stride 49, coprime 32 ->
// conflict-free STS). TMA tile stays packed in natural channel order.
__device__ __half g_featsT16[P_ * C_];

// ---------------------------------------------------------------------------
// Kernel 1: tiled transpose feats (C, P) fp32 -> featsT (P, Cperm) fp16.
// ---------------------------------------------------------------------------
__global__ void transpose_kernel(const float* __restrict__ in) {
    __shared__ float tile[32][33];
    int p  = blockIdx.x * 32 + threadIdx.x;   // spatial index (coalesced read)
    int cb = blockIdx.y * 32;
#pragma unroll
    for (int j = 0; j < 4; j++)
        tile[threadIdx.y + j * 8][threadIdx.x] = in[(cb + threadIdx.y + j * 8) * P_ + p];
    __syncthreads();
    int pp = blockIdx.x * 32 + threadIdx.y;
    int cc = cb + threadIdx.x;                // channel index
    int b4 = cc >> 7;
    int w7 = cc & 127;
    int dst = (b4 << 7) + ((w7 & 63) << 1) + (w7 >> 6);
#pragma unroll
    for (int j = 0; j < 4; j++)
        g_featsT16[(size_t)(pp + j * 8) * C_ + dst] =
            __float2half_rn(tile[threadIdx.x][threadIdx.y + j * 8]);
}

// ---------------------------------------------------------------------------
// Kernel 2: one block = (box-group of NBOX, channel-quarter). 256 threads.
//   Per box: meta (double-buffered) -> gather 13 pos/thread into regs
//   (overlapping the previous box's TMA drain) -> wait -> STS -> TMA store.
// ---------------------------------------------------------------------------
__global__ __launch_bounds__(256, 6)
void roi_kernel(const float* __restrict__ boxes,
                const int* __restrict__ imhp,
                const int* __restrict__ imwp,
                float* __restrict__ out) {
    extern __shared__ unsigned char smem_raw[];
    int4*  s_off = (int4*)smem_raw;                        // [2][49] half2-unit offsets
    int4*  s_wh  = (int4*)(smem_raw + 2 * NPOS * 16);      // [2][49] duplicated half2 weights
    float* stage = (float*)(smem_raw + 4 * NPOS * 16);     // packed (128,49) fp32 tile

    const int bh   = blockIdx.x;
    const int base = (bh >> 2) * NBOX;                     // first box of this group
    const int q4   = bh & 3;                               // channel quarter
    const int ch0u = q4 * 64;                              // half2-unit base of quarter
    const int t = threadIdx.x;

    const int g  = t & 63;
    const int qq = t >> 6;
    const int ps = qq * 12;                                // 0,12,24,36 (1-pos overlap ok)
    const __half2* __restrict__ Fg = (const __half2*)g_featsT16 + g;

    uint32_t stage_sa;
    asm("{ .reg .u64 tmp; cvta.to.shared.u64 tmp, %1; cvt.u32.u64 %0, tmp; }"
        : "=r"(stage_sa) : "l"(stage));

#pragma unroll 1
    for (int i = 0; i < NBOX; i++) {
        const int b   = base + i;
        const int buf = (i & 1) * NPOS;

        // Phase 0: metadata for box b into buffer (i&1).
        if (t < NPOS) {
            float xc = boxes[b * 4 + 0], yc = boxes[b * 4 + 1];
            float w  = boxes[b * 4 + 2], h  = boxes[b * 4 + 3];
            int imh = *imhp, imw = *imwp;
            float inv_w = 1.f / (float)(imw - 1);
            float inv_h = 1.f / (float)(imh - 1);
            int iy = t / 7, ix = t - iy * 7;
            float txv = -1.f + (float)ix * (2.f / 6.f);
            float tyv = -1.f + (float)iy * (2.f / 6.f);
            float gx = (2.f * xc - (float)(imw - 1)) * inv_w + (w * inv_w) * txv;
            float gy = (2.f * yc - (float)(imh - 1)) * inv_h + (h * inv_h) * tyv;
            float px = (gx + 1.f) * 0.5f * (float)(WF - 1);
            float py = (gy + 1.f) * 0.5f * (float)(HF - 1);
            float x0f = floorf(px), y0f = floorf(py);
            float fx = px - x0f,   fy = py - y0f;
            // zero-padding outside the feature map: weight *= validity
            float vx0 = (x0f >=  0.f && x0f <= (float)(WF - 1)) ? 1.f : 0.f;
            float vx1 = (x0f >= -1.f && x0f <= (float)(WF - 2)) ? 1.f : 0.f;
            float vy0 = (y0f >=  0.f && y0f <= (float)(HF - 1)) ? 1.f : 0.f;
            float vy1 = (y0f >= -1.f && y0f <= (float)(HF - 2)) ? 1.f : 0.f;
            float wx0 = (1.f - fx) * vx0, wx1 = fx * vx1;
            float wy0 = (1.f - fy) * vy0, wy1 = fy * vy1;
            int cx0 = (int)fminf(fmaxf(x0f,       0.f), (float)(WF - 1));
            int cx1 = (int)fminf(fmaxf(x0f + 1.f, 0.f), (float)(WF - 1));
            int cy0 = (int)fminf(fmaxf(y0f,       0.f), (float)(HF - 1));
            int cy1 = (int)fminf(fmaxf(y0f + 1.f, 0.f), (float)(HF - 1));
            s_off[buf + t] = make_int4((cy0 * WF + cx0) * C2H + ch0u,
                                       (cy0 * WF + cx1) * C2H + ch0u,
                                       (cy1 * WF + cx0) * C2H + ch0u,
                                       (cy1 * WF + cx1) * C2H + ch0u);
            __half2 hw0 = __float2half2_rn(wy0 * wx0);
            __half2 hw1 = __float2half2_rn(wy0 * wx1);
            __half2 hw2 = __float2half2_rn(wy1 * wx0);
            __half2 hw3 = __float2half2_rn(wy1 * wx1);
            s_wh[buf + t] = make_int4(*reinterpret_cast<int*>(&hw0),
                                      *reinterpret_cast<int*>(&hw1),
                                      *reinterpret_cast<int*>(&hw2),
                                      *reinterpret_cast<int*>(&hw3));
        }
        __syncthreads();

        // Phase 1: gather 13 positions into registers (no smem stores here) —
        // this long phase overlaps the previous box's TMA drain.
        const int4* __restrict__ so  = s_off + buf + ps;
        const int4* __restrict__ swh = s_wh + buf + ps;
        __half2 acc[13];
#pragma unroll
        for (int j = 0; j < 13; j++) {
            int4 o  = so[j];
            int4 wv = swh[j];
            __half2 w0 = *reinterpret_cast<__half2*>(&wv.x);
            __half2 w1 = *reinterpret_cast<__half2*>(&wv.y);
            __half2 w2 = *reinterpret_cast<__half2*>(&wv.z);
            __half2 w3 = *reinterpret_cast<__half2*>(&wv.w);
            __half2 a = __hmul2(w0, __ldg(Fg + o.x));
            a = __hfma2(w1, __ldg(Fg + o.y), a);
            a = __hfma2(w2, __ldg(Fg + o.z), a);
            acc[j] = __hfma2(w3, __ldg(Fg + o.w), a);
        }

        // Ensure previous TMA store finished reading stage before overwriting.
        if (t == 0)
            asm volatile("cp.async.bulk.wait_group 0;" ::: "memory");
        __syncthreads();

        // Phase 2: conflict-free STS burst (rows g and g+64, stride 49 words).
        float* sp = stage + g * NPOS + ps;
#pragma unroll
        for (int j = 0; j < 13; j++) {
            float2 f = __half22float2(acc[j]);
            sp[j]             = f.x;           // channel 128*q4 + g
            sp[64 * NPOS + j] = f.y;           // channel 128*q4 + g + 64
        }

        __syncthreads();
        asm volatile("fence.proxy.async.shared::cta;" ::: "memory");

        // Phase 3: one 1D bulk TMA store of the packed 25,088-byte tile.
        if (t == 0) {
            float* gdst = out + (size_t)b * (C_ * NPOS) + (size_t)q4 * TILE_FLOATS;
            asm volatile(
                "cp.async.bulk.global.shared::cta.bulk_group [%0], [%1], %2;"
                :: "l"(gdst), "r"(stage_sa), "n"(TILE_FLOATS * 4) : "memory");
            asm volatile("cp.async.bulk.commit_group;" ::: "memory");
        }
    }

    // Drain the last store before the CTA retires (smem may be reallocated).
    if (t == 0)
        asm volatile("cp.async.bulk.wait_group 0;" ::: "memory");
}

extern "C" void kernel_launch(void* const* d_in, const int* in_sizes, int n_in,
                              void* d_out, int out_size) {
    const float* feats = (const float*)d_in[0];
    const float* boxes = (const float*)d_in[1];
    const int*   imh   = (const int*)d_in[2];
    const int*   imw   = (const int*)d_in[3];
    float*       out   = (float*)d_out;

    int B = in_sizes[1] / 4;

    transpose_kernel<<<dim3(P_ / 32, C_ / 32), dim3(32, 8)>>>(feats);

    cudaFuncSetAttribute(roi_kernel, cudaFuncAttributeMaxDynamicSharedMemorySize, SMEM_BYTES);
    roi_kernel<<<(B / NBOX) * 4, 256, SMEM_BYTES>>>(boxes, imh, imw, out);
}

// round 17
// speedup vs baseline: 1.2412x; 1.2412x over previous
#include <cuda_runtime.h>
#include <cuda_fp16.h>
#include <cstdint>

#define C_      512
#define C2H     (C_ / 2)           // half2 units per spatial position (256)
#define HF      64
#define WF      256
#define P_      (HF * WF)          // 16384 spatial positions
#define NPOS    49                 // 7x7 samples
#define CH_BLK  128                // channels per block (box split in quarters)
#define TILE_FLOATS (CH_BLK * NPOS)               // 6272 floats = 25088 bytes
#define SMEM_BYTES  (2 * NPOS * 16 + TILE_FLOATS * 4)  // 1568 + 25088 = 26656

// Transposed feats in fp16: (Hf*Wf, C), natural channel order.
__device__ __half g_featsT16[P_ * C_];

// ---------------------------------------------------------------------------
// Kernel 1: transpose feats (C, P) fp32 -> featsT (P, C) fp16.
// Block = 32 positions x 128 channels, tile stride 132 floats (16B-aligned
// rows). Load: 4 coalesced LDG (consecutive channels) -> STS.128 at
// tile[lane][4*c4] (addr16 = 33*lane + c4: conflict-free). Write: LDS.128 at
// tile[p][4*cg] (fixed p, consecutive cg: conflict-free, aligned) -> 2x half2
// -> 8-byte STG, 256B/warp contiguous.
// ---------------------------------------------------------------------------
__global__ __launch_bounds__(256)
void transpose_kernel(const float* __restrict__ in) {
    __shared__ float tile[32][132];            // stride 132: 16B-aligned rows
    const int pb = blockIdx.x * 32;
    const int cb = blockIdx.y * 128;
    const int lane = threadIdx.x & 31;         // p within tile
    const int cy   = threadIdx.x >> 5;         // 0..7

    // Load: thread handles channel groups c4 = cy, cy+8, cy+16, cy+24
    // (4 consecutive channels each; every LDG coalesced 128B over p).
#pragma unroll
    for (int i = 0; i < 4; i++) {
        int c4 = cy + i * 8;                   // group of 4 channels
        const float* src = in + (size_t)(cb + 4 * c4) * P_ + pb + lane;
        float4 v;
        v.x = src[0 * P_];
        v.y = src[1 * P_];
        v.z = src[2 * P_];
        v.w = src[3 * P_];
        *reinterpret_cast<float4*>(&tile[lane][4 * c4]) = v;
    }
    __syncthreads();

    // Write: 4 iterations, each thread emits one half4 (8B) of 4 channels.
#pragma unroll
    for (int w = 0; w < 4; w++) {
        int idx = w * 256 + threadIdx.x;
        int p   = idx >> 5;                    // 0..31 (fixed per warp)
        int cg  = idx & 31;                    // half4 group within 128 channels
        float4 v = *reinterpret_cast<const float4*>(&tile[p][cg * 4]);
        __half2 h0 = __floats2half2_rn(v.x, v.y);
        __half2 h1 = __floats2half2_rn(v.z, v.w);
        uint2 u = make_uint2(*reinterpret_cast<uint32_t*>(&h0),
                             *reinterpret_cast<uint32_t*>(&h1));
        *reinterpret_cast<uint2*>(
            g_featsT16 + (size_t)(pb + p) * C_ + cb + cg * 4) = u;
    }
}

// ---------------------------------------------------------------------------
// Gather a chunk of LEN positions. Bilinear combine in native half2
// (1 HMUL2 + 3 HFMA2 per position), convert the result once, STS burst.
// (R12 verbatim — best measured configuration, 94.7 us.)
// ---------------------------------------------------------------------------
template <int LEN>
__device__ __forceinline__ void gather_chunk(const __half2* __restrict__ Fg,
                                             const int4*    __restrict__ so,
                                             const int4*    __restrict__ swh,
                                             float* __restrict__ sp, int kk) {
    __half2 acc[LEN];
#pragma unroll
    for (int j = 0; j < LEN; j++) {
        int4 o  = so[kk + j];
        int4 wv = swh[kk + j];                 // 4 duplicated-half2 weights
        __half2 w0 = *reinterpret_cast<__half2*>(&wv.x);
        __half2 w1 = *reinterpret_cast<__half2*>(&wv.y);
        __half2 w2 = *reinterpret_cast<__half2*>(&wv.z);
        __half2 w3 = *reinterpret_cast<__half2*>(&wv.w);
        __half2 a = __hmul2(w0, __ldg(Fg + o.x));
        a = __hfma2(w1, __ldg(Fg + o.y), a);
        a = __hfma2(w2, __ldg(Fg + o.z), a);
        acc[j] = __hfma2(w3, __ldg(Fg + o.w), a);
    }
#pragma unroll
    for (int j = 0; j < LEN; j++) {
        float2 f = __half22float2(acc[j]);
        sp[kk + j]        = f.x;
        sp[NPOS + kk + j] = f.y;
    }
}

// ---------------------------------------------------------------------------
// Kernel 2: one block = (box, channel-quarter). 256 threads, 128 channels.
// (R12 verbatim.)
// ---------------------------------------------------------------------------
__global__ __launch_bounds__(256, 6)
void roi_kernel(const float* __restrict__ boxes,
                const int* __restrict__ imhp,
                const int* __restrict__ imwp,
                float* __restrict__ out) {
    extern __shared__ unsigned char smem_raw[];
    int4* s_off = (int4*)smem_raw;                         // 49 x int4 (half2-unit offsets)
    int4* s_wh  = (int4*)(smem_raw + NPOS * 16);           // 49 x 4 duplicated half2 weights
    float* stage = (float*)(smem_raw + 2 * NPOS * 16);     // packed (128,49) fp32 tile

    const int bh = blockIdx.x;
    const int b  = bh >> 2;
    const int ch0h = (bh & 3) * (CH_BLK / 2);              // half2-unit channel base
    const int t = threadIdx.x;

    if (t < NPOS) {
        float xc = boxes[b * 4 + 0], yc = boxes[b * 4 + 1];
        float w  = boxes[b * 4 + 2], h  = boxes[b * 4 + 3];
        int imh = *imhp, imw = *imwp;
        float inv_w = 1.f / (float)(imw - 1);
        float inv_h = 1.f / (float)(imh - 1);
        int iy = t / 7, ix = t - iy * 7;
        float txv = -1.f + (float)ix * (2.f / 6.f);
        float tyv = -1.f + (float)iy * (2.f / 6.f);
        float gx = (2.f * xc - (float)(imw - 1)) * inv_w + (w * inv_w) * txv;
        float gy = (2.f * yc - (float)(imh - 1)) * inv_h + (h * inv_h) * tyv;
        float px = (gx + 1.f) * 0.5f * (float)(WF - 1);
        float py = (gy + 1.f) * 0.5f * (float)(HF - 1);
        float x0f = floorf(px), y0f = floorf(py);
        float fx = px - x0f,   fy = py - y0f;
        // zero-padding outside the feature map: weight *= validity
        float vx0 = (x0f >=  0.f && x0f <= (float)(WF - 1)) ? 1.f : 0.f;
        float vx1 = (x0f >= -1.f && x0f <= (float)(WF - 2)) ? 1.f : 0.f;
        float vy0 = (y0f >=  0.f && y0f <= (float)(HF - 1)) ? 1.f : 0.f;
        float vy1 = (y0f >= -1.f && y0f <= (float)(HF - 2)) ? 1.f : 0.f;
        float wx0 = (1.f - fx) * vx0, wx1 = fx * vx1;
        float wy0 = (1.f - fy) * vy0, wy1 = fy * vy1;
        int cx0 = (int)fminf(fmaxf(x0f,       0.f), (float)(WF - 1));
        int cx1 = (int)fminf(fmaxf(x0f + 1.f, 0.f), (float)(WF - 1));
        int cy0 = (int)fminf(fmaxf(y0f,       0.f), (float)(HF - 1));
        int cy1 = (int)fminf(fmaxf(y0f + 1.f, 0.f), (float)(HF - 1));
        // offsets in half2 units, channel-quarter base folded in
        s_off[t] = make_int4((cy0 * WF + cx0) * C2H + ch0h,
                             (cy0 * WF + cx1) * C2H + ch0h,
                             (cy1 * WF + cx0) * C2H + ch0h,
                             (cy1 * WF + cx1) * C2H + ch0h);
        // duplicated-half2 weights, packed as int4
        __half2 hw0 = __float2half2_rn(wy0 * wx0);
        __half2 hw1 = __float2half2_rn(wy0 * wx1);
        __half2 hw2 = __float2half2_rn(wy1 * wx0);
        __half2 hw3 = __float2half2_rn(wy1 * wx1);
        s_wh[t] = make_int4(*reinterpret_cast<int*>(&hw0),
                            *reinterpret_cast<int*>(&hw1),
                            *reinterpret_cast<int*>(&hw2),
                            *reinterpret_cast<int*>(&hw3));
    }
    __syncthreads();

    // Phase 1: 13 positions per group (ps = q*12), chunks of 6+7.
    const int g  = t & 63;
    const int q  = t >> 6;
    const int ps = q * 12;                                  // 0,12,24,36 (overlap ok)
    const __half2* __restrict__ Fg = (const __half2*)g_featsT16 + g;
    const int4*    __restrict__ so  = s_off + ps;
    const int4*    __restrict__ swh = s_wh + ps;
    float* sp = stage + (2 * g) * NPOS + ps;

    gather_chunk<6>(Fg, so, swh, sp, 0);
    gather_chunk<7>(Fg, so, swh, sp, 6);

    // Make generic-proxy smem writes visible to the async (TMA) proxy.
    __syncthreads();
    asm volatile("fence.proxy.async.shared::cta;" ::: "memory");

    // Phase 2: one 1D bulk TMA store of the packed 25,088-byte quarter-tile.
    if (t == 0) {
        uint32_t saddr;
        asm("{ .reg .u64 tmp; cvta.to.shared.u64 tmp, %1; cvt.u32.u64 %0, tmp; }"
            : "=r"(saddr) : "l"(stage));
        float* gdst = out + (size_t)bh * TILE_FLOATS;
        asm volatile(
            "cp.async.bulk.global.shared::cta.bulk_group [%0], [%1], %2;"
            :: "l"(gdst), "r"(saddr), "n"(TILE_FLOATS * 4) : "memory");
        asm volatile("cp.async.bulk.commit_group;" ::: "memory");
        asm volatile("cp.async.bulk.wait_group 0;" ::: "memory");
    }
}

extern "C" void kernel_launch(void* const* d_in, const int* in_sizes, int n_in,
                              void* d_out, int out_size) {
    const float* feats = (const float*)d_in[0];
    const float* boxes = (const float*)d_in[1];
    const int*   imh   = (const int*)d_in[2];
    const int*   imw   = (const int*)d_in[3];
    float*       out   = (float*)d_out;

    int B = in_sizes[1] / 4;

    transpose_kernel<<<dim3(P_ / 32, C_ / 128), 256>>>(feats);

    cudaFuncSetAttribute(roi_kernel, cudaFuncAttributeMaxDynamicSharedMemorySize, SMEM_BYTES);
    roi_kernel<<<B * 4, 256, SMEM_BYTES>>>(boxes, imh, imw, out);
}